// round 13
// baseline (speedup 1.0000x reference)
#include <cuda_runtime.h>
#include <cstdint>

#define SEQ   2048
#define BATCH 128
#define INP   64
#define HID   256
#define GH    1024   // 4*HID
#define OUTD  64
#define NBG   16     // batch groups (8 batches each)
#define NUG   8      // unit groups  (32 units / 128 gate rows each)

typedef unsigned long long ull;

// packed 2xfp32 FMA (B300: FFMA-3reg is half rate; f32x2 restores full rate)
#define FMA2(d, a, b) asm("fma.rn.f32x2 %0, %1, %2, %0;" : "+l"(d) : "l"(a), "l"(b))

__device__ __forceinline__ float hsum2(ull v) {
    float2 f = *(float2*)&v;
    return f.x + f.y;
}

// ---------------- scratch (static device arrays; no cudaMalloc) --------
__device__ float g_hs[(size_t)SEQ * BATCH * HID];  // h history (streamed)
__device__ float g_hx[2][BATCH * HID];             // hot h exchange (L2)
__device__ unsigned g_flag[NBG * NUG * 32];        // per-CTA publish flags (128B apart)
__device__ unsigned g_cnt;                          // one-shot global barriers
__device__ volatile unsigned g_gen;

// =============================================================
// Single persistent kernel: fused LSTM scan + readout GEMM.
// 128 CTAs = 16 bgroups(8 b) x 8 ugroups(32 u / 128 gate rows).
// R13: per-thread poll+reload (each thread acquires only the flag
// of the rank whose h-float4 it stages) — 3 barriers/step (was 4),
// straggler skew absorbed by x-GEMV after each thread's own poll.
// W row stride 296 (==8 mod 32): W LDS tiles 2 conflict-free
// wavefronts (was ~3 with WS=268).
// =============================================================
#define WS   296   // W_hh row stride (floats); 296 % 32 == 8 -> 2-wf W loads
#define KSK  68    // W_hh/H ks-slice skew
#define HSK  548   // H ks-slice stride = 8*68 + 4
#define LST  132   // L batch stride
#define WXS  84    // W_ih row stride (floats)
#define KSX  20    // W_ih/x ks-slice skew
#define XSK  164   // x ks-slice stride = 8*20 + 4
#define XBUF (4 * XSK)   // 656 floats per x buffer

#define SM_W    0
#define SM_WX   (128 * WS)             // 37888
#define SM_H    (SM_WX + 128 * WXS)    // 48640
#define SM_L    (SM_H + 4 * HSK)       // 50832
#define SM_X    (SM_L + 8 * LST)       // 51888
// scan layout ends at SM_X + 2*XBUF = 53200.
// readout reuses [0..) for Wout tiles and [SM_H..SM_H+4864) for Hs tile.
#define SM_TOT  53504                  // floats = 214016 B

__device__ __forceinline__ void grid_barrier(int t) {
    if (t == 0) {
        unsigned cur = g_gen;
        __threadfence();
        if (atomicAdd(&g_cnt, 1u) == 127u) {
            atomicExch(&g_cnt, 0u);
            __threadfence();
            g_gen = cur + 1u;
        } else {
            while (g_gen == cur) { }
        }
        __threadfence();
    }
    __syncthreads();
}

__global__ void __launch_bounds__(512, 1)
k_lstm(const float* __restrict__ x, const float* __restrict__ h0,
       const float* __restrict__ c0, const float* __restrict__ Whh,
       const float* __restrict__ Wih, const float* __restrict__ bias,
       const float* __restrict__ Wout, const float* __restrict__ bout,
       float* __restrict__ out)
{
    extern __shared__ float smR[];
    float* Wsm  = smR + SM_W;    // W_hh [row 0..127][ks*68 + k]
    float* Wxsm = smR + SM_WX;   // W_ih [row 0..127][ks*20 + k]
    float* Hsm  = smR + SM_H;    // h    [ks][b*68 + k]
    float* Lsm  = smR + SM_L;    // lin  [b][row]
    float* Xsm  = smR + SM_X;    // x    [par][ks][b*20 + k]

    const int t     = threadIdx.x;
    const int bgrp  = blockIdx.x >> 3;      // 0..15
    const int urank = blockIdx.x & 7;       // 0..7
    const int b0g   = bgrp << 3;            // global batch base
    const int u0    = urank << 5;           // global unit base

    const int w    = t >> 5, lane = t & 31;
    const int rp   = (w << 2) + (lane >> 3);     // row pair 0..63
    const int ks   = (lane >> 1) & 3;            // K quarter
    const int bp   = lane & 1;                   // batch half

    // ---- reset my publish flag ----
    unsigned* myflag = &g_flag[(bgrp * NUG + urank) * 32];
    if (t == 0) *myflag = 0u;

    // ---- load W_hh slice into SMEM once ----
    for (int idx = t; idx < 128 * 64; idx += 512) {
        int r = idx >> 6, c4 = idx & 63;
        int grow = ((r >> 5) << 8) + u0 + (r & 31);
        float4 v = ((const float4*)Whh)[(size_t)grow * 64 + c4];
        int kss = c4 >> 4, kk = (c4 & 15) << 2;
        *(float4*)(Wsm + r * WS + kss * KSK + kk) = v;
    }
    // ---- load W_ih slice into SMEM once ----
    for (int idx = t; idx < 128 * 16; idx += 512) {
        int r = idx >> 4, c4 = idx & 15;
        int grow = ((r >> 5) << 8) + u0 + (r & 31);
        float4 v = ((const float4*)Wih)[(size_t)grow * 16 + c4];
        int kss = c4 >> 2, kk = (c4 & 3) << 2;
        *(float4*)(Wxsm + r * WXS + kss * KSX + kk) = v;
    }
    // ---- init Hsm from h0 ----
    {
        int b = t >> 6, c4 = t & 63;
        float4 v = ((const float4*)h0)[(size_t)(b0g + b) * 64 + c4];
        int kss = c4 >> 4, kk = (c4 & 15) << 2;
        *(float4*)(Hsm + kss * HSK + b * KSK + kk) = v;
    }
    // ---- init Xsm[0] from x[0]; prefetch x[1] into regs (t<128) ----
    float4 xr = make_float4(0.f, 0.f, 0.f, 0.f);
    if (t < 128) {
        int b = t >> 4, c4 = t & 15;
        float4 v = ((const float4*)x)[(size_t)(b0g + b) * 16 + c4];
        int kss = c4 >> 2, kk = (c4 & 3) << 2;
        *(float4*)(Xsm + kss * XSK + b * KSX + kk) = v;
        xr = ((const float4*)x)[(size_t)(BATCH + b0g + b) * 16 + c4];
    }

    // ---- gate-thread state (t < 256) ----
    const int gb  = t >> 5;
    const int gu  = t & 31;
    const int ugt = u0 + gu;
    float creg = 0.f, bi = 0.f, bf = 0.f, bg = 0.f, bo = 0.f;
    if (t < 256) {
        creg = c0[(size_t)(b0g + gb) * HID + ugt];
        bi = bias[0 * HID + ugt];
        bf = bias[1 * HID + ugt];
        bg = bias[2 * HID + ugt];
        bo = bias[3 * HID + ugt];
    }

    // flags-zeroed-before-anyone-publishes barrier (replay-safe)
    grid_barrier(t);

    const float* Wp   = Wsm  + (rp * 2 + 0) * WS  + ks * KSK;
    const float* Wp1  = Wsm  + (rp * 2 + 1) * WS  + ks * KSK;
    const float* Hp   = Hsm  + ks * HSK + (bp << 2) * KSK;
    const float* Wxp  = Wxsm + (rp * 2 + 0) * WXS + ks * KSX;
    const float* Wxp1 = Wxsm + (rp * 2 + 1) * WXS + ks * KSX;

    // ---- per-thread reload assignment: (batch br, float4 c4r, src rank) ----
    const int br  = t >> 6;          // 0..7
    const int c4r = t & 63;          // float4 index within 256 units
    const unsigned* srcflag = &g_flag[(bgrp * NUG + (c4r >> 3)) * 32];
    float* hsm_dst = Hsm + (c4r >> 4) * HSK + br * KSK + ((c4r & 15) << 2);
    const float* hx_src0 = &g_hx[0][(b0g + br) * HID + (c4r << 2)];
    const float* hx_src1 = &g_hx[1][(b0g + br) * HID + (c4r << 2)];

    #pragma unroll 1
    for (int step = 0; step < SEQ; step++) {
        const int par = step & 1;

        // ---- 1: per-thread poll src flag, reload my float4 into Hsm ----
        if (step > 0) {
            unsigned v;
            do {
                asm volatile("ld.acquire.gpu.u32 %0, [%1];"
                             : "=r"(v) : "l"(srcflag) : "memory");
            } while (v < (unsigned)step);
            float4 hv4 = *(const float4*)((par == 0) ? hx_src1 : hx_src0);
            *(float4*)hsm_dst = hv4;
        }

        // ---- 2: x-part GEMV (independent of h; absorbs poll skew) ----
        ull acc00 = 0, acc01 = 0, acc02 = 0, acc03 = 0;
        ull acc10 = 0, acc11 = 0, acc12 = 0, acc13 = 0;
        {
            const float* Xq = Xsm + par * XBUF + ks * XSK + (bp << 2) * KSX;
            #pragma unroll
            for (int kx = 0; kx < 4; kx++) {
                ulonglong2 w0 = *(const ulonglong2*)(Wxp  + kx * 4);
                ulonglong2 w1 = *(const ulonglong2*)(Wxp1 + kx * 4);
                ulonglong2 hv;
                hv = *(const ulonglong2*)(Xq + 0 * KSX + kx * 4);
                FMA2(acc00, w0.x, hv.x); FMA2(acc00, w0.y, hv.y);
                FMA2(acc10, w1.x, hv.x); FMA2(acc10, w1.y, hv.y);
                hv = *(const ulonglong2*)(Xq + 1 * KSX + kx * 4);
                FMA2(acc01, w0.x, hv.x); FMA2(acc01, w0.y, hv.y);
                FMA2(acc11, w1.x, hv.x); FMA2(acc11, w1.y, hv.y);
                hv = *(const ulonglong2*)(Xq + 2 * KSX + kx * 4);
                FMA2(acc02, w0.x, hv.x); FMA2(acc02, w0.y, hv.y);
                FMA2(acc12, w1.x, hv.x); FMA2(acc12, w1.y, hv.y);
                hv = *(const ulonglong2*)(Xq + 3 * KSX + kx * 4);
                FMA2(acc03, w0.x, hv.x); FMA2(acc03, w0.y, hv.y);
                FMA2(acc13, w1.x, hv.x); FMA2(acc13, w1.y, hv.y);
            }
        }
        __syncthreads();   // Hsm staged by all threads

        // ---- 3: h-part GEMV accumulate ----
        #pragma unroll
        for (int k4 = 0; k4 < 16; k4++) {
            ulonglong2 w0 = *(const ulonglong2*)(Wp  + k4 * 4);
            ulonglong2 w1 = *(const ulonglong2*)(Wp1 + k4 * 4);
            ulonglong2 hv;
            hv = *(const ulonglong2*)(Hp + 0 * KSK + k4 * 4);
            FMA2(acc00, w0.x, hv.x); FMA2(acc00, w0.y, hv.y);
            FMA2(acc10, w1.x, hv.x); FMA2(acc10, w1.y, hv.y);
            hv = *(const ulonglong2*)(Hp + 1 * KSK + k4 * 4);
            FMA2(acc01, w0.x, hv.x); FMA2(acc01, w0.y, hv.y);
            FMA2(acc11, w1.x, hv.x); FMA2(acc11, w1.y, hv.y);
            hv = *(const ulonglong2*)(Hp + 2 * KSK + k4 * 4);
            FMA2(acc02, w0.x, hv.x); FMA2(acc02, w0.y, hv.y);
            FMA2(acc12, w1.x, hv.x); FMA2(acc12, w1.y, hv.y);
            hv = *(const ulonglong2*)(Hp + 3 * KSK + k4 * 4);
            FMA2(acc03, w0.x, hv.x); FMA2(acc03, w0.y, hv.y);
            FMA2(acc13, w1.x, hv.x); FMA2(acc13, w1.y, hv.y);
        }

        // ---- 4: reduce over 4 ks lanes, write Lsm ----
        {
            const int r0 = rp * 2, bb = bp << 2;
            float v;
            v = hsum2(acc00); v += __shfl_xor_sync(~0u, v, 2); v += __shfl_xor_sync(~0u, v, 4);
            if (ks == 0) Lsm[(bb + 0) * LST + r0] = v;
            v = hsum2(acc01); v += __shfl_xor_sync(~0u, v, 2); v += __shfl_xor_sync(~0u, v, 4);
            if (ks == 0) Lsm[(bb + 1) * LST + r0] = v;
            v = hsum2(acc02); v += __shfl_xor_sync(~0u, v, 2); v += __shfl_xor_sync(~0u, v, 4);
            if (ks == 0) Lsm[(bb + 2) * LST + r0] = v;
            v = hsum2(acc03); v += __shfl_xor_sync(~0u, v, 2); v += __shfl_xor_sync(~0u, v, 4);
            if (ks == 0) Lsm[(bb + 3) * LST + r0] = v;
            v = hsum2(acc10); v += __shfl_xor_sync(~0u, v, 2); v += __shfl_xor_sync(~0u, v, 4);
            if (ks == 0) Lsm[(bb + 0) * LST + r0 + 1] = v;
            v = hsum2(acc11); v += __shfl_xor_sync(~0u, v, 2); v += __shfl_xor_sync(~0u, v, 4);
            if (ks == 0) Lsm[(bb + 1) * LST + r0 + 1] = v;
            v = hsum2(acc12); v += __shfl_xor_sync(~0u, v, 2); v += __shfl_xor_sync(~0u, v, 4);
            if (ks == 0) Lsm[(bb + 2) * LST + r0 + 1] = v;
            v = hsum2(acc13); v += __shfl_xor_sync(~0u, v, 2); v += __shfl_xor_sync(~0u, v, 4);
            if (ks == 0) Lsm[(bb + 3) * LST + r0 + 1] = v;
        }
        __syncthreads();

        // ---- 5: gates (t<256) publish to g_hx; x-pipe (t<128) ----
        float hh = 0.f;
        if (t < 256) {
            const float* Lb = Lsm + gb * LST;
            float iv = Lb[gu]      + bi;
            float fv = Lb[32 + gu] + bf;
            float gv = Lb[64 + gu] + bg;
            float ov = Lb[96 + gu] + bo;
            float ig = 1.f / (1.f + __expf(-iv));
            float fg = 1.f / (1.f + __expf(-fv));
            float gg = tanhf(gv);
            float og = 1.f / (1.f + __expf(-ov));
            float cc = fg * creg + ig * gg;
            creg = cc;
            hh = og * tanhf(cc);
            g_hx[par][(b0g + gb) * HID + ugt] = hh;   // hot exchange (L2)
        }
        if (t < 128 && step + 1 < SEQ) {
            int b = t >> 4, c4 = t & 15;
            int kss = c4 >> 2, kk = (c4 & 3) << 2;
            *(float4*)(Xsm + (par ^ 1) * XBUF + kss * XSK + b * KSX + kk) = xr;
            if (step + 2 < SEQ)
                xr = ((const float4*)x)[(size_t)((step + 2) * BATCH + b0g + b) * 16 + c4];
        }
        __syncthreads();

        // ---- 6: single-thread release publish (orders g_hx only) ----
        if (t == 0) {
            unsigned nv = (unsigned)(step + 1);
            asm volatile("st.release.gpu.u32 [%0], %1;"
                         :: "l"(myflag), "r"(nv) : "memory");
        }
        // ---- 7: history store AFTER release (unordered, drains bg) ----
        if (t < 256)
            __stcs(&g_hs[((size_t)step * BATCH + b0g + gb) * HID + ugt], hh);
    }

    // ================= readout: out = hs @ Wout^T + bout =================
    __threadfence();      // make all g_hs stores visible
    grid_barrier(t);

    ulonglong2* WoS = (ulonglong2*)smR;            // [kc][64][19]
    ulonglong2* HsS = (ulonglong2*)(smR + SM_H);   // [64][19]

    for (int idx = t; idx < 4096; idx += 512) {
        int kc = idx >> 10, rem = idx & 1023, rr = rem >> 4, c = rem & 15;
        WoS[(kc * 64 + rr) * 19 + c] =
            ((const ulonglong2*)Wout)[(size_t)rr * 64 + kc * 16 + c];
    }
    const int tx  = t & 15;
    const int tyr = t >> 4;   // 0..31
    float bo4[4];
    #pragma unroll
    for (int j = 0; j < 4; j++) bo4[j] = __ldg(&bout[tx + 16 * j]);
    __syncthreads();

    for (int tile = 0; tile < 32; tile++) {
        size_t m0 = ((size_t)blockIdx.x * 32 + tile) * 64;
        ull ac[2][4];
        #pragma unroll
        for (int i = 0; i < 2; i++)
            #pragma unroll
            for (int j = 0; j < 4; j++) ac[i][j] = 0ull;

        for (int kc = 0; kc < 4; kc++) {
            __syncthreads();
            for (int idx = t; idx < 1024; idx += 512) {
                int rr = idx >> 4, c = idx & 15;
                HsS[rr * 19 + c] =
                    ((const ulonglong2*)g_hs)[(m0 + rr) * 64 + kc * 16 + c];
            }
            __syncthreads();
            #pragma unroll
            for (int k4 = 0; k4 < 16; k4++) {
                ulonglong2 a0 = HsS[tyr * 19 + k4];
                ulonglong2 a1 = HsS[(tyr + 32) * 19 + k4];
                #pragma unroll
                for (int j = 0; j < 4; j++) {
                    ulonglong2 b2 = WoS[(kc * 64 + tx + 16 * j) * 19 + k4];
                    FMA2(ac[0][j], a0.x, b2.x); FMA2(ac[0][j], a0.y, b2.y);
                    FMA2(ac[1][j], a1.x, b2.x); FMA2(ac[1][j], a1.y, b2.y);
                }
            }
        }
        #pragma unroll
        for (int i = 0; i < 2; i++) {
            size_t m = m0 + tyr + 32 * i;
            #pragma unroll
            for (int j = 0; j < 4; j++)
                out[m * OUTD + tx + 16 * j] = hsum2(ac[i][j]) + bo4[j];
        }
    }
}

// =============================================================
extern "C" void kernel_launch(void* const* d_in, const int* in_sizes, int n_in,
                              void* d_out, int out_size)
{
    (void)in_sizes; (void)n_in; (void)out_size;
    const float* x    = (const float*)d_in[0];
    const float* h0   = (const float*)d_in[1];
    const float* c0   = (const float*)d_in[2];
    const float* Wih  = (const float*)d_in[3];
    const float* Whh  = (const float*)d_in[4];
    const float* b    = (const float*)d_in[5];
    const float* Wout = (const float*)d_in[6];
    const float* bout = (const float*)d_in[7];
    float* out = (float*)d_out;

    const int smB = SM_TOT * 4;   // 214016 B

    cudaFuncSetAttribute(k_lstm, cudaFuncAttributeMaxDynamicSharedMemorySize, smB);

    k_lstm<<<NBG * NUG, 512, smB>>>(x, h0, c0, Whh, Wih, b, Wout, bout, out);
}

// round 14
// speedup vs baseline: 1.0507x; 1.0507x over previous
#include <cuda_runtime.h>
#include <cstdint>

#define SEQ   2048
#define BATCH 128
#define INP   64
#define HID   256
#define GH    1024   // 4*HID
#define OUTD  64
#define NBG   16     // batch groups (8 batches each)
#define NUG   8      // unit groups  (32 units / 128 gate rows each)

typedef unsigned long long ull;

// packed 2xfp32 FMA (B300: FFMA-3reg is half rate; f32x2 restores full rate)
#define FMA2(d, a, b) asm("fma.rn.f32x2 %0, %1, %2, %0;" : "+l"(d) : "l"(a), "l"(b))

__device__ __forceinline__ float hsum2(ull v) {
    float2 f = *(float2*)&v;
    return f.x + f.y;
}

#define BAR_ARRIVE(id, cnt) \
    asm volatile("bar.arrive %0, %1;" :: "r"(id), "r"(cnt) : "memory")
#define BAR_SYNCN(id, cnt) \
    asm volatile("bar.sync %0, %1;"   :: "r"(id), "r"(cnt) : "memory")

// ---------------- scratch (static device arrays; no cudaMalloc) --------
__device__ float g_hs[(size_t)SEQ * BATCH * HID];  // h history (streamed)
__device__ float g_hx[2][BATCH * HID];             // hot h exchange (L2)
__device__ unsigned g_flag[NBG * NUG * 32];        // per-CTA publish flags (128B apart)
__device__ unsigned g_cnt;                          // one-shot global barriers
__device__ volatile unsigned g_gen;

// =============================================================
// Single persistent kernel: warp-specialized LSTM scan + readout.
// 128 CTAs = 16 bgroups(8 b) x 8 ugroups(32 u / 128 gate rows).
// warps 0-7  (256 thr): comm+gates — gates, publish, release,
//   poll, LDG exchange, stage Hsm, stage x.
// warps 8-15 (256 thr): compute — x-GEMV + h-GEMV (full K per
//   thread: 1 row x 4 batches -> no shfl reduce), Lsm.
// Coupling: named barriers GATE(1) Lsm-ready, HRDY(2) h-staged,
// CBAR(3) comm-local. The sync chain overlaps the x-GEMV.
// =============================================================
#define WR    260   // W_hh row stride (floats)
#define WXR   68    // W_ih row stride
#define HS2   260   // H batch stride
#define HBUF2 (8 * HS2)      // 2080 floats per H parity buffer
#define LST2  132   // L batch stride
#define XB    68    // x batch stride
#define XQ    (8 * XB)       // 544 floats per x buffer (x4 quad)

#define SM_W   0
#define SM_WX  (128 * WR)            // 33280
#define SM_H   (SM_WX + 128 * WXR)   // 41984
#define SM_L   (SM_H + 2 * HBUF2)    // 46144
#define SM_X   (SM_L + 8 * LST2)     // 47200
#define SM_TOT (SM_X + 4 * XQ + 32)  // 49408 floats = 197632 B

#define BARID_GATE 1
#define BARID_HRDY 2
#define BARID_CBAR 3

__device__ __forceinline__ void grid_barrier(int t) {
    if (t == 0) {
        unsigned cur = g_gen;
        __threadfence();
        if (atomicAdd(&g_cnt, 1u) == 127u) {
            atomicExch(&g_cnt, 0u);
            __threadfence();
            g_gen = cur + 1u;
        } else {
            while (g_gen == cur) { }
        }
        __threadfence();
    }
    __syncthreads();
}

__global__ void __launch_bounds__(512, 1)
k_lstm(const float* __restrict__ x, const float* __restrict__ h0,
       const float* __restrict__ c0, const float* __restrict__ Whh,
       const float* __restrict__ Wih, const float* __restrict__ bias,
       const float* __restrict__ Wout, const float* __restrict__ bout,
       float* __restrict__ out)
{
    extern __shared__ float smR[];
    float* Wsm  = smR + SM_W;    // W_hh [row r][k 0..255], stride WR
    float* Wxsm = smR + SM_WX;   // W_ih [row r][k 0..63], stride WXR
    float* Hsm  = smR + SM_H;    // h [par][b][k 0..255]
    float* Lsm  = smR + SM_L;    // lin [b][row 0..127]
    float* Xsm  = smR + SM_X;    // x [q 0..3][b][k 0..63]

    const int t     = threadIdx.x;
    const int bgrp  = blockIdx.x >> 3;      // 0..15
    const int urank = blockIdx.x & 7;       // 0..7
    const int b0g   = bgrp << 3;            // global batch base
    const int u0    = urank << 5;           // global unit base

    // ---- reset my publish flag ----
    unsigned* myflag = &g_flag[(bgrp * NUG + urank) * 32];
    if (t == 0) *myflag = 0u;

    // ---- load W_hh slice (128 rows x 256 K, linear k) ----
    for (int idx = t; idx < 128 * 64; idx += 512) {
        int r = idx >> 6, c4 = idx & 63;
        int grow = ((r >> 5) << 8) + u0 + (r & 31);
        float4 v = ((const float4*)Whh)[(size_t)grow * 64 + c4];
        *(float4*)(Wsm + r * WR + (c4 << 2)) = v;
    }
    // ---- load W_ih slice (128 rows x 64 K) ----
    for (int idx = t; idx < 128 * 16; idx += 512) {
        int r = idx >> 4, c4 = idx & 15;
        int grow = ((r >> 5) << 8) + u0 + (r & 31);
        float4 v = ((const float4*)Wih)[(size_t)grow * 16 + c4];
        *(float4*)(Wxsm + r * WXR + (c4 << 2)) = v;
    }
    // ---- init Hsm[0] from h0 ----
    {
        int b = t >> 6, c4 = t & 63;
        float4 v = ((const float4*)h0)[(size_t)(b0g + b) * 64 + c4];
        *(float4*)(Hsm + b * HS2 + (c4 << 2)) = v;
    }
    // ---- init Xsm[0]=x(0), Xsm[1]=x(1); xr = x(2) (t<128) ----
    float4 xr = make_float4(0.f, 0.f, 0.f, 0.f);
    if (t < 128) {
        int b = t >> 4, c4 = t & 15;
        *(float4*)(Xsm + 0 * XQ + b * XB + (c4 << 2)) =
            ((const float4*)x)[(size_t)(b0g + b) * 16 + c4];
        *(float4*)(Xsm + 1 * XQ + b * XB + (c4 << 2)) =
            ((const float4*)x)[(size_t)(BATCH + b0g + b) * 16 + c4];
        xr = ((const float4*)x)[(size_t)(2 * BATCH + b0g + b) * 16 + c4];
    }

    // ---- comm-thread state (t < 256) ----
    const int b_c = t >> 5;
    const int u_c = t & 31;
    const int ugt = u0 + u_c;
    float creg = 0.f, bi = 0.f, bf = 0.f, bg = 0.f, bo = 0.f;
    if (t < 256) {
        creg = c0[(size_t)(b0g + b_c) * HID + ugt];
        bi = bias[0 * HID + ugt];
        bf = bias[1 * HID + ugt];
        bg = bias[2 * HID + ugt];
        bo = bias[3 * HID + ugt];
    }
    // staging assignment: 2 float4s per comm thread (j0 ranks 0-3, j1 ranks 4-7)
    const int j0 = u_c, j1 = u_c + 32;
    const unsigned* f0 = &g_flag[(bgrp * NUG + (j0 >> 3)) * 32];
    const unsigned* f1 = &g_flag[(bgrp * NUG + (j1 >> 3)) * 32];
    const int hxoff0 = (b0g + b_c) * HID + (j0 << 2);
    const int hxoff1 = (b0g + b_c) * HID + (j1 << 2);

    grid_barrier(t);   // flags zeroed everywhere before first publish

    if (t < 256) {
        // ======================= COMM + GATES =======================
        #pragma unroll 1
        for (int step = 0; step < SEQ; step++) {
            const int par = step & 1;
            BAR_SYNCN(BARID_GATE, 512);          // Lsm(step) ready

            const float* Lb = Lsm + b_c * LST2;
            float iv = Lb[u_c]      + bi;
            float fv = Lb[32 + u_c] + bf;
            float gv = Lb[64 + u_c] + bg;
            float ov = Lb[96 + u_c] + bo;
            float ig = 1.f / (1.f + __expf(-iv));
            float fg = 1.f / (1.f + __expf(-fv));
            float gg = tanhf(gv);
            float og = 1.f / (1.f + __expf(-ov));
            float cc = fg * creg + ig * gg;
            creg = cc;
            float hh = og * tanhf(cc);
            g_hx[par][(b0g + b_c) * HID + ugt] = hh;

            // x stage 2 ahead (t<128)
            if (t < 128 && step + 2 < SEQ) {
                int b = t >> 4, c4 = t & 15;
                *(float4*)(Xsm + ((step + 2) & 3) * XQ + b * XB + (c4 << 2)) = xr;
                if (step + 3 < SEQ)
                    xr = ((const float4*)x)[(size_t)((step + 3) * BATCH + b0g + b) * 16 + c4];
            }

            BAR_SYNCN(BARID_CBAR, 256);          // all publishes issued
            if (t == 0) {
                unsigned nv = (unsigned)(step + 1);
                asm volatile("st.release.gpu.u32 [%0], %1;"
                             :: "l"(myflag), "r"(nv) : "memory");
            }
            __stcs(&g_hs[((size_t)step * BATCH + b0g + b_c) * HID + ugt], hh);

            if (step + 1 < SEQ) {
                unsigned v;
                do {
                    asm volatile("ld.acquire.gpu.u32 %0, [%1];"
                                 : "=r"(v) : "l"(f0) : "memory");
                } while (v < (unsigned)(step + 1));
                float4 hva = *(const float4*)&g_hx[par][hxoff0];
                do {
                    asm volatile("ld.acquire.gpu.u32 %0, [%1];"
                                 : "=r"(v) : "l"(f1) : "memory");
                } while (v < (unsigned)(step + 1));
                float4 hvb = *(const float4*)&g_hx[par][hxoff1];
                float* Hd = Hsm + ((step + 1) & 1) * HBUF2 + b_c * HS2;
                *(float4*)(Hd + (j0 << 2)) = hva;
                *(float4*)(Hd + (j1 << 2)) = hvb;
                BAR_ARRIVE(BARID_HRDY, 512);     // h(step) staged for step+1
            }
        }
    } else {
        // ========================= COMPUTE ==========================
        const int ct = t - 256;
        const int r  = ct >> 1;        // gate row 0..127
        const int bp = ct & 1;         // batch half
        const int bb = bp << 2;        // batch base 0 or 4
        const float* Wrow  = Wsm  + r * WR;
        const float* Wxrow = Wxsm + r * WXR;

        #pragma unroll 1
        for (int step = 0; step < SEQ; step++) {
            // ---- x-GEMV first (overlaps comm's publish->poll->stage) ----
            ull a0 = 0, a1 = 0, a2 = 0, a3 = 0;
            {
                const float* Xq = Xsm + (step & 3) * XQ + bb * XB;
                #pragma unroll
                for (int k2 = 0; k2 < 16; k2++) {
                    ulonglong2 wv = *(const ulonglong2*)(Wxrow + (k2 << 2));
                    ulonglong2 hv;
                    hv = *(const ulonglong2*)(Xq + 0 * XB + (k2 << 2));
                    FMA2(a0, wv.x, hv.x); FMA2(a0, wv.y, hv.y);
                    hv = *(const ulonglong2*)(Xq + 1 * XB + (k2 << 2));
                    FMA2(a1, wv.x, hv.x); FMA2(a1, wv.y, hv.y);
                    hv = *(const ulonglong2*)(Xq + 2 * XB + (k2 << 2));
                    FMA2(a2, wv.x, hv.x); FMA2(a2, wv.y, hv.y);
                    hv = *(const ulonglong2*)(Xq + 3 * XB + (k2 << 2));
                    FMA2(a3, wv.x, hv.x); FMA2(a3, wv.y, hv.y);
                }
            }
            if (step > 0) BAR_SYNCN(BARID_HRDY, 512);   // h(step-1) staged

            // ---- h-GEMV: full K=256, 1 row x 4 batches ----
            {
                const float* Hb = Hsm + (step & 1) * HBUF2 + bb * HS2;
                #pragma unroll 8
                for (int k2 = 0; k2 < 64; k2++) {
                    ulonglong2 wv = *(const ulonglong2*)(Wrow + (k2 << 2));
                    ulonglong2 hv;
                    hv = *(const ulonglong2*)(Hb + 0 * HS2 + (k2 << 2));
                    FMA2(a0, wv.x, hv.x); FMA2(a0, wv.y, hv.y);
                    hv = *(const ulonglong2*)(Hb + 1 * HS2 + (k2 << 2));
                    FMA2(a1, wv.x, hv.x); FMA2(a1, wv.y, hv.y);
                    hv = *(const ulonglong2*)(Hb + 2 * HS2 + (k2 << 2));
                    FMA2(a2, wv.x, hv.x); FMA2(a2, wv.y, hv.y);
                    hv = *(const ulonglong2*)(Hb + 3 * HS2 + (k2 << 2));
                    FMA2(a3, wv.x, hv.x); FMA2(a3, wv.y, hv.y);
                }
            }
            // ---- Lsm: 4 scalar stores (no shfl reduce needed) ----
            Lsm[(bb + 0) * LST2 + r] = hsum2(a0);
            Lsm[(bb + 1) * LST2 + r] = hsum2(a1);
            Lsm[(bb + 2) * LST2 + r] = hsum2(a2);
            Lsm[(bb + 3) * LST2 + r] = hsum2(a3);
            BAR_ARRIVE(BARID_GATE, 512);
        }
    }

    // ================= readout: out = hs @ Wout^T + bout =================
    __threadfence();
    grid_barrier(t);

    ulonglong2* WoS = (ulonglong2*)smR;            // [kc][64][19]
    ulonglong2* HsS = (ulonglong2*)(smR + SM_H);   // [64][19]

    for (int idx = t; idx < 4096; idx += 512) {
        int kc = idx >> 10, rem = idx & 1023, rr = rem >> 4, c = rem & 15;
        WoS[(kc * 64 + rr) * 19 + c] =
            ((const ulonglong2*)Wout)[(size_t)rr * 64 + kc * 16 + c];
    }
    const int tx  = t & 15;
    const int tyr = t >> 4;   // 0..31
    float bo4[4];
    #pragma unroll
    for (int j = 0; j < 4; j++) bo4[j] = __ldg(&bout[tx + 16 * j]);
    __syncthreads();

    for (int tile = 0; tile < 32; tile++) {
        size_t m0 = ((size_t)blockIdx.x * 32 + tile) * 64;
        ull ac[2][4];
        #pragma unroll
        for (int i = 0; i < 2; i++)
            #pragma unroll
            for (int j = 0; j < 4; j++) ac[i][j] = 0ull;

        for (int kc = 0; kc < 4; kc++) {
            __syncthreads();
            for (int idx = t; idx < 1024; idx += 512) {
                int rr = idx >> 4, c = idx & 15;
                HsS[rr * 19 + c] =
                    ((const ulonglong2*)g_hs)[(m0 + rr) * 64 + kc * 16 + c];
            }
            __syncthreads();
            #pragma unroll
            for (int k4 = 0; k4 < 16; k4++) {
                ulonglong2 a0 = HsS[tyr * 19 + k4];
                ulonglong2 a1 = HsS[(tyr + 32) * 19 + k4];
                #pragma unroll
                for (int j = 0; j < 4; j++) {
                    ulonglong2 b2 = WoS[(kc * 64 + tx + 16 * j) * 19 + k4];
                    FMA2(ac[0][j], a0.x, b2.x); FMA2(ac[0][j], a0.y, b2.y);
                    FMA2(ac[1][j], a1.x, b2.x); FMA2(ac[1][j], a1.y, b2.y);
                }
            }
        }
        #pragma unroll
        for (int i = 0; i < 2; i++) {
            size_t m = m0 + tyr + 32 * i;
            #pragma unroll
            for (int j = 0; j < 4; j++)
                out[m * OUTD + tx + 16 * j] = hsum2(ac[i][j]) + bo4[j];
        }
    }
}

// =============================================================
extern "C" void kernel_launch(void* const* d_in, const int* in_sizes, int n_in,
                              void* d_out, int out_size)
{
    (void)in_sizes; (void)n_in; (void)out_size;
    const float* x    = (const float*)d_in[0];
    const float* h0   = (const float*)d_in[1];
    const float* c0   = (const float*)d_in[2];
    const float* Wih  = (const float*)d_in[3];
    const float* Whh  = (const float*)d_in[4];
    const float* b    = (const float*)d_in[5];
    const float* Wout = (const float*)d_in[6];
    const float* bout = (const float*)d_in[7];
    float* out = (float*)d_out;

    const int smB = SM_TOT * 4;   // 197632 B

    cudaFuncSetAttribute(k_lstm, cudaFuncAttributeMaxDynamicSharedMemorySize, smB);

    k_lstm<<<NBG * NUG, 512, smB>>>(x, h0, c0, Whh, Wih, b, Wout, bout, out);
}